// round 6
// baseline (speedup 1.0000x reference)
#include <cuda_runtime.h>
#include <math.h>

// Problem constants
#define BB 64
#define SS 1024
#define HH 128
#define AA 8
#define WIN 5
#define PADW 2
#define STILE 64             // s-tile for logits kernel (4 blocks/SM)
#define CTILE 64             // s-chunk per ctx block
#define NSUB 4               // s-subgroups per ctx block (reduced in-block)
#define NCH (SS / CTILE)     // 16 coarse chunks
#define GROWS (STILE + 4)    // 68 padded rows in logits tile

// Scratch (no allocations allowed)
// Packed G: [h][w][8] with inner order (a0,a4,a1,a5,a2,a6,a3,a7) so a 16B load
// yields two 64-bit (G[a],G[a+4]) pairs for fma.rn.f32x2.
__device__ float4 gGp4[HH * WIN * 2];                // 128*5*8 floats
__device__ float gLogits[AA * BB * SS];              // [a][b][s]
__device__ float gCtxPart[NCH * AA * BB * HH];       // [sc][a][b][h]  (4.2MB)

__device__ __forceinline__ void fma2(unsigned long long& acc,
                                     unsigned long long d2,
                                     unsigned long long g2) {
    asm("fma.rn.f32x2 %0, %1, %2, %3;" : "=l"(acc) : "l"(d2), "l"(g2), "l"(acc));
}
__device__ __forceinline__ unsigned long long dup2(float v) {
    unsigned long long r;
    asm("mov.b64 %0, {%1, %1};" : "=l"(r) : "f"(v));
    return r;
}
__device__ __forceinline__ unsigned long long pk2(float lo, float hi) {
    unsigned long long r;
    asm("mov.b64 %0, {%1, %2};" : "=l"(r) : "f"(lo), "f"(hi));
    return r;
}
__device__ __forceinline__ void unpk(unsigned long long p, float& lo, float& hi) {
    asm("mov.b64 {%0, %1}, %2;" : "=f"(lo), "=f"(hi) : "l"(p));
}

// ---------------------------------------------------------------------------
// K1: G[a,h,w] = sum_f P[a,h,f] * E[a,f,w]; packed scatter to gGp4.
// grid = (A, 4), block = 128. thread: h = hg*32 + (t>>2), f-quarter q = t&3.
// Direct float4 gmem reads, shfl reduction over the 4 f-quarters.
// ---------------------------------------------------------------------------
__global__ void k_prep(const float* __restrict__ P, const float* __restrict__ E) {
    __shared__ float Esm[HH * WIN];
    int a = blockIdx.x, hg = blockIdx.y, t = threadIdx.x;
    int h = hg * 32 + (t >> 2), q = t & 3;

    for (int i = t; i < HH * WIN; i += 128)
        Esm[i] = E[(size_t)a * HH * WIN + i];
    __syncthreads();

    const float4* Pp = (const float4*)(P + (size_t)a * HH * HH + h * HH + q * 32);
    float g[WIN] = {0.f, 0.f, 0.f, 0.f, 0.f};
    #pragma unroll
    for (int i = 0; i < 8; ++i) {
        float4 p = Pp[i];
        int f0 = q * 32 + i * 4;
        #pragma unroll
        for (int w = 0; w < WIN; ++w) {
            g[w] += p.x * Esm[(f0 + 0) * WIN + w];
            g[w] += p.y * Esm[(f0 + 1) * WIN + w];
            g[w] += p.z * Esm[(f0 + 2) * WIN + w];
            g[w] += p.w * Esm[(f0 + 3) * WIN + w];
        }
    }
    #pragma unroll
    for (int w = 0; w < WIN; ++w) {
        g[w] += __shfl_xor_sync(0xffffffffu, g[w], 1);
        g[w] += __shfl_xor_sync(0xffffffffu, g[w], 2);
    }
    if (q == 0) {
        float* Gp = (float*)gGp4;
        #pragma unroll
        for (int w = 0; w < WIN; ++w)
            Gp[(h * WIN + w) * 8 + (a & 3) * 2 + (a >> 2)] = g[w];
    }
}

// ---------------------------------------------------------------------------
// K2: logits[a,b,s] = sum_w sum_h doc[b, s+w-2, h] * G[a,h,w]
// lane -> 2 consecutive s, warp -> 32-h split, f32x2 accumulators.
// dsm pitch 128, swizzle col = h ^ ((row>>1)&31): conflict-free for the
// stride-32 fill writes AND the 2-row-stride tap reads.
// grid = (S/64, B) = (16,64), block = 128, smem 55KB -> 4 blocks/SM.
// ---------------------------------------------------------------------------
__global__ void __launch_bounds__(128) k_logits(const float* __restrict__ doc) {
    extern __shared__ float sm[];
    float* dsm = sm;                        // [GROWS][128] swizzled
    float* Gsm = sm + GROWS * HH;           // [H*WIN*8] packed pairs
    int b  = blockIdx.y;
    int s0 = blockIdx.x * STILE;
    int t  = threadIdx.x;
    int wid = t >> 5, lane = t & 31;

    // Copy packed G (5120 floats) via float4
    {
        const float4* src = gGp4;
        float4* dst = (float4*)Gsm;
        #pragma unroll
        for (int i = t; i < HH * WIN * 2; i += 128) dst[i] = src[i];
    }

    // Tile fill: warp handles rows wid, wid+4, ...; lane loads cols l+32m.
    const float* db = doc + (size_t)b * SS * HH;
    for (int row = wid; row < GROWS; row += 4) {
        int gs = s0 - PADW + row;
        int swz = (row >> 1) & 31;
        const float* src = db + (size_t)gs * HH;
        #pragma unroll
        for (int m = 0; m < 4; ++m) {
            int c = lane + 32 * m;
            float v = (gs >= 0 && gs < SS) ? src[c] : 0.f;
            dsm[row * HH + (c ^ swz)] = v;
        }
    }
    __syncthreads();

    // Main loop: warp's 32-h range, lane's 2 consecutive s.
    int h0 = wid * 32;
    int st0 = 2 * lane;
    unsigned long long acc[2][4];
    #pragma unroll
    for (int i = 0; i < 2; ++i)
        #pragma unroll
        for (int p = 0; p < 4; ++p) acc[i][p] = 0ull;

    #pragma unroll 4
    for (int hh = 0; hh < 32; ++hh) {
        int h = h0 + hh;
        unsigned long long d[6];
        #pragma unroll
        for (int r = 0; r < 6; ++r) {
            int row = st0 + r;
            d[r] = dup2(dsm[row * HH + (h ^ ((row >> 1) & 31))]);
        }
        const float* gh = &Gsm[h * (WIN * 8)];
        #pragma unroll
        for (int w = 0; w < WIN; ++w) {
            ulonglong2 g01 = *(const ulonglong2*)(gh + w * 8);
            ulonglong2 g23 = *(const ulonglong2*)(gh + w * 8 + 4);
            #pragma unroll
            for (int si = 0; si < 2; ++si) {
                fma2(acc[si][0], d[si + w], g01.x);
                fma2(acc[si][1], d[si + w], g01.y);
                fma2(acc[si][2], d[si + w], g23.x);
                fma2(acc[si][3], d[si + w], g23.y);
            }
        }
    }

    // Cross-warp h-reduction: red[st][33], slot = a*4 + wid.
    __syncthreads();
    float* red = sm;   // 64*33 floats, fits in dsm region
    #pragma unroll
    for (int si = 0; si < 2; ++si) {
        int st = st0 + si;
        #pragma unroll
        for (int p = 0; p < 4; ++p) {
            float lo, hi;
            unpk(acc[si][p], lo, hi);
            red[st * 33 + p * 4 + wid] = lo;           // aspect p
            red[st * 33 + (p + 4) * 4 + wid] = hi;     // aspect p+4
        }
    }
    __syncthreads();

    int st = t & 63, ah = t >> 6;
    #pragma unroll
    for (int j = 0; j < 4; ++j) {
        int a = ah * 4 + j;
        const float* rp = &red[st * 33 + a * 4];
        float v = rp[0] + rp[1] + rp[2] + rp[3];
        gLogits[((size_t)a * BB + b) * SS + s0 + st] = v;
    }
}

// ---------------------------------------------------------------------------
// K3: attn = softmax_s(logits); write to out[b][a][s]
// grid = A*B (row = a*B + b), block = 256
// ---------------------------------------------------------------------------
__global__ void k_softmax(float* __restrict__ out) {
    int row = blockIdx.x;
    int a = row >> 6;
    int b = row & 63;
    const float* lg = gLogits + (size_t)row * SS;
    int t = threadIdx.x;

    float v[4];
    float m = -3.4e38f;
    #pragma unroll
    for (int i = 0; i < 4; ++i) { v[i] = lg[t + i * 256]; m = fmaxf(m, v[i]); }

    __shared__ float redm[8];
    #pragma unroll
    for (int o = 16; o > 0; o >>= 1) m = fmaxf(m, __shfl_xor_sync(0xffffffffu, m, o));
    if ((t & 31) == 0) redm[t >> 5] = m;
    __syncthreads();
    m = redm[0];
    #pragma unroll
    for (int i = 1; i < 8; ++i) m = fmaxf(m, redm[i]);

    float sl = 0.f;
    #pragma unroll
    for (int i = 0; i < 4; ++i) { v[i] = __expf(v[i] - m); sl += v[i]; }
    __shared__ float reds[8];
    #pragma unroll
    for (int o = 16; o > 0; o >>= 1) sl += __shfl_xor_sync(0xffffffffu, sl, o);
    if ((t & 31) == 0) reds[t >> 5] = sl;
    __syncthreads();
    float tot = 0.f;
    #pragma unroll
    for (int i = 0; i < 8; ++i) tot += reds[i];
    float inv = 1.0f / tot;

    float* op = out + ((size_t)b * AA + a) * SS;
    #pragma unroll
    for (int i = 0; i < 4; ++i) op[t + i * 256] = v[i] * inv;
}

// ---------------------------------------------------------------------------
// K4: ctx partials. Thread = (h-quad = t&31, s-sub = t>>5). The 4 s-subgroup
// partials are reduced IN-BLOCK through smem, so only NCH=16 coarse partials
// hit DRAM (4.2MB instead of 16.8MB).
// grid = (16, 64), block = 128.
// ---------------------------------------------------------------------------
__global__ void __launch_bounds__(128) k_ctx(const float* __restrict__ doc,
                                             const float* __restrict__ attn) {
    int b = blockIdx.y, sc = blockIdx.x;
    int t = threadIdx.x;
    int hq = t & 31, sg = t >> 5;

    __shared__ float asmem[AA * CTILE];
    __shared__ float4 rbuf[NSUB][AA][32];   // 16KB
    #pragma unroll
    for (int i = t; i < AA * CTILE; i += 128) {
        int a = i >> 6, s = i & 63;
        asmem[i] = attn[((size_t)b * AA + a) * SS + sc * CTILE + s];
    }
    __syncthreads();

    const float4* dp = (const float4*)(doc + ((size_t)b * SS + sc * CTILE) * HH) + hq;
    unsigned long long acc[AA][2];
    #pragma unroll
    for (int a = 0; a < AA; ++a) { acc[a][0] = 0ull; acc[a][1] = 0ull; }

    #pragma unroll 8
    for (int s = sg; s < CTILE; s += NSUB) {
        float4 dv = dp[s * (HH / 4)];            // coalesced LDG.128
        unsigned long long dxy = pk2(dv.x, dv.y);
        unsigned long long dzw = pk2(dv.z, dv.w);
        #pragma unroll
        for (int a = 0; a < AA; ++a) {
            unsigned long long av = dup2(asmem[a * CTILE + s]);  // broadcast
            fma2(acc[a][0], dxy, av);
            fma2(acc[a][1], dzw, av);
        }
    }

    #pragma unroll
    for (int a = 0; a < AA; ++a) {
        float4 o;
        unpk(acc[a][0], o.x, o.y);
        unpk(acc[a][1], o.z, o.w);
        rbuf[sg][a][hq] = o;
    }
    __syncthreads();

    // Reduce over sg and store: thread t -> a = t>>4, two h-quads.
    int a = t >> 4, j = t & 15;
    #pragma unroll
    for (int k = 0; k < 2; ++k) {
        int q = j * 2 + k;
        float4 v0 = rbuf[0][a][q], v1 = rbuf[1][a][q];
        float4 v2 = rbuf[2][a][q], v3 = rbuf[3][a][q];
        float4 o;
        o.x = (v0.x + v1.x) + (v2.x + v3.x);
        o.y = (v0.y + v1.y) + (v2.y + v3.y);
        o.z = (v0.z + v1.z) + (v2.z + v3.z);
        o.w = (v0.w + v1.w) + (v2.w + v3.w);
        float4* op = (float4*)(gCtxPart + (((size_t)sc * AA + a) * BB + b) * HH) + q;
        *op = o;                                  // coalesced STG.128
    }
}

// ---------------------------------------------------------------------------
// K5: rep[b,a,f] = sum_h ctx[a,b,h] * P[a,h,f], ctx reduced over 16 partials
// grid = B*A (blk = b*A + a), block = 128 (thread = f)
// ---------------------------------------------------------------------------
__global__ void k_rep(const float* __restrict__ P, float* __restrict__ out) {
    int blk = blockIdx.x;
    int a = blk & 7, b = blk >> 3;
    int f = threadIdx.x;
    __shared__ float csm[HH];
    float c = 0.f;
    #pragma unroll
    for (int sc = 0; sc < NCH; ++sc)
        c += gCtxPart[(((size_t)sc * AA + a) * BB + b) * HH + f];
    csm[f] = c;
    __syncthreads();

    float acc = 0.f;
    const float* Pp = P + (size_t)a * HH * HH + f;
    #pragma unroll 8
    for (int h = 0; h < HH; ++h) acc += csm[h] * Pp[(size_t)h * HH];

    out[(size_t)BB * AA * SS + ((size_t)b * AA + a) * HH + f] = acc;
}

// ---------------------------------------------------------------------------
extern "C" void kernel_launch(void* const* d_in, const int* in_sizes, int n_in,
                              void* d_out, int out_size) {
    const float* doc = (const float*)d_in[0];   // (B,S,H)
    const float* E   = (const float*)d_in[1];   // (A, WIN*H)
    const float* P   = (const float*)d_in[2];   // (A,H,H)
    float* out = (float*)d_out;                 // [attn (B,A,S) | rep (B,A,H)]

    size_t sm2 = (size_t)(GROWS * HH + HH * WIN * 8) * sizeof(float);  // ~55.3 KB
    cudaFuncSetAttribute(k_logits, cudaFuncAttributeMaxDynamicSharedMemorySize, (int)sm2);

    k_prep<<<dim3(AA, 4), 128>>>(P, E);
    k_logits<<<dim3(SS / STILE, BB), 128, sm2>>>(doc);
    k_softmax<<<AA * BB, 256>>>(out);
    k_ctx<<<dim3(SS / CTILE, BB), 128>>>(doc, out);
    k_rep<<<BB * AA, 128>>>(P, out);
}

// round 7
// speedup vs baseline: 1.4117x; 1.4117x over previous
#include <cuda_runtime.h>
#include <math.h>

// Problem constants
#define BB 64
#define SS 1024
#define HH 128
#define AA 8
#define WIN 5
#define PADW 2
#define STILE 128            // s-tile for logits kernel
#define GROWS (STILE + 4)    // 132 padded rows in logits tile
#define CCH 128              // s per ctx block
#define NCH (SS / CCH)       // 8 coarse ctx chunks
#define RPW 1028             // ctx rbuf pitch (floats): 16B-aligned, bank-scattered

// Scratch (no allocations allowed)
// Packed G: [h][w][8] with inner order (a0,a4,a1,a5,a2,a6,a3,a7) so a 16B load
// yields two 64-bit (G[a],G[a+4]) pairs for fma.rn.f32x2.
__device__ float4 gGp4[HH * WIN * 2];                // 128*5*8 floats
__device__ float gLogits[AA * BB * SS];              // [a][b][s]
__device__ float gCtxPart[NCH * AA * BB * HH];       // [sc][a][b][h]  (2.1MB)

__device__ __forceinline__ void fma2(unsigned long long& acc,
                                     unsigned long long d2,
                                     unsigned long long g2) {
    asm("fma.rn.f32x2 %0, %1, %2, %3;" : "=l"(acc) : "l"(d2), "l"(g2), "l"(acc));
}
__device__ __forceinline__ unsigned long long dup2(float v) {
    unsigned long long r;
    asm("mov.b64 %0, {%1, %1};" : "=l"(r) : "f"(v));
    return r;
}
__device__ __forceinline__ unsigned long long pk2(float lo, float hi) {
    unsigned long long r;
    asm("mov.b64 %0, {%1, %2};" : "=l"(r) : "f"(lo), "f"(hi));
    return r;
}
__device__ __forceinline__ void unpk(unsigned long long p, float& lo, float& hi) {
    asm("mov.b64 {%0, %1}, %2;" : "=f"(lo), "=f"(hi) : "l"(p));
}

// ---------------------------------------------------------------------------
// K1: G[a,h,w] = sum_f P[a,h,f] * E[a,f,w]; packed scatter to gGp4.
// grid = (A, 4), block = 128. thread: h = hg*32 + (t>>2), f-quarter q = t&3.
// ---------------------------------------------------------------------------
__global__ void k_prep(const float* __restrict__ P, const float* __restrict__ E) {
    __shared__ float Esm[HH * WIN];
    int a = blockIdx.x, hg = blockIdx.y, t = threadIdx.x;
    int h = hg * 32 + (t >> 2), q = t & 3;

    for (int i = t; i < HH * WIN; i += 128)
        Esm[i] = E[(size_t)a * HH * WIN + i];
    __syncthreads();

    const float4* Pp = (const float4*)(P + (size_t)a * HH * HH + h * HH + q * 32);
    float g[WIN] = {0.f, 0.f, 0.f, 0.f, 0.f};
    #pragma unroll
    for (int i = 0; i < 8; ++i) {
        float4 p = Pp[i];
        int f0 = q * 32 + i * 4;
        #pragma unroll
        for (int w = 0; w < WIN; ++w) {
            g[w] += p.x * Esm[(f0 + 0) * WIN + w];
            g[w] += p.y * Esm[(f0 + 1) * WIN + w];
            g[w] += p.z * Esm[(f0 + 2) * WIN + w];
            g[w] += p.w * Esm[(f0 + 3) * WIN + w];
        }
    }
    #pragma unroll
    for (int w = 0; w < WIN; ++w) {
        g[w] += __shfl_xor_sync(0xffffffffu, g[w], 1);
        g[w] += __shfl_xor_sync(0xffffffffu, g[w], 2);
    }
    if (q == 0) {
        float* Gp = (float*)gGp4;
        #pragma unroll
        for (int w = 0; w < WIN; ++w)
            Gp[(h * WIN + w) * 8 + (a & 3) * 2 + (a >> 2)] = g[w];
    }
}

// ---------------------------------------------------------------------------
// K2: logits[a,b,s] = sum_w sum_h doc[b, s+w-2, h] * G[a,h,w]
// (R5-proven version) lane -> 4 consecutive s, warp -> 32-h split.
// dsm pitch 128, XOR swizzle col = h ^ ((row>>2)&31).
// grid = (S/128, B), block = 128, smem 88KB.
// ---------------------------------------------------------------------------
__global__ void __launch_bounds__(128) k_logits(const float* __restrict__ doc) {
    extern __shared__ float sm[];
    float* dsm = sm;                         // [GROWS][128] swizzled
    float* Gsm = sm + GROWS * HH;            // [H*WIN*8] packed pairs
    int b  = blockIdx.y;
    int s0 = blockIdx.x * STILE;
    int t  = threadIdx.x;
    int wid = t >> 5, lane = t & 31;

    {
        const float4* src = gGp4;
        float4* dst = (float4*)Gsm;
        #pragma unroll
        for (int i = t; i < HH * WIN * 2; i += HH) dst[i] = src[i];
    }

    const float* db = doc + (size_t)b * SS * HH;
    for (int row = wid; row < GROWS; row += 4) {
        int gs = s0 - PADW + row;
        int swz = (row >> 2) & 31;
        const float* src = db + (size_t)gs * HH;
        #pragma unroll
        for (int m = 0; m < 4; ++m) {
            int c = lane + 32 * m;
            float v = (gs >= 0 && gs < SS) ? src[c] : 0.f;
            dsm[row * HH + (c ^ swz)] = v;
        }
    }
    __syncthreads();

    int h0 = wid * 32;
    int st0 = 4 * lane;
    unsigned long long acc[4][4];
    #pragma unroll
    for (int i = 0; i < 4; ++i)
        #pragma unroll
        for (int p = 0; p < 4; ++p) acc[i][p] = 0ull;

    #pragma unroll 2
    for (int hh = 0; hh < 32; ++hh) {
        int h = h0 + hh;
        unsigned long long d[8];
        #pragma unroll
        for (int r = 0; r < 8; ++r) {
            int row = st0 + r;
            d[r] = dup2(dsm[row * HH + (h ^ ((row >> 2) & 31))]);
        }
        const float* gh = &Gsm[h * (WIN * 8)];
        #pragma unroll
        for (int w = 0; w < WIN; ++w) {
            ulonglong2 g01 = *(const ulonglong2*)(gh + w * 8);
            ulonglong2 g23 = *(const ulonglong2*)(gh + w * 8 + 4);
            #pragma unroll
            for (int si = 0; si < 4; ++si) {
                fma2(acc[si][0], d[si + w], g01.x);
                fma2(acc[si][1], d[si + w], g01.y);
                fma2(acc[si][2], d[si + w], g23.x);
                fma2(acc[si][3], d[si + w], g23.y);
            }
        }
    }

    __syncthreads();
    float* red = sm;   // 128*33 floats, fits in dsm region
    #pragma unroll
    for (int si = 0; si < 4; ++si) {
        int st = st0 + si;
        #pragma unroll
        for (int p = 0; p < 4; ++p) {
            float lo, hi;
            unpk(acc[si][p], lo, hi);
            red[st * 33 + p * 4 + wid] = lo;           // aspect p
            red[st * 33 + (p + 4) * 4 + wid] = hi;     // aspect p+4
        }
    }
    __syncthreads();

    int st = t;
    #pragma unroll
    for (int a = 0; a < AA; ++a) {
        const float* rp = &red[st * 33 + a * 4];
        float v = rp[0] + rp[1] + rp[2] + rp[3];
        gLogits[((size_t)a * BB + b) * SS + s0 + st] = v;
    }
}

// ---------------------------------------------------------------------------
// K3: attn = softmax_s(logits); write to out[b][a][s]
// grid = A*B (row = a*B + b), block = 256
// ---------------------------------------------------------------------------
__global__ void k_softmax(float* __restrict__ out) {
    int row = blockIdx.x;
    int a = row >> 6;
    int b = row & 63;
    const float* lg = gLogits + (size_t)row * SS;
    int t = threadIdx.x;

    float v[4];
    float m = -3.4e38f;
    #pragma unroll
    for (int i = 0; i < 4; ++i) { v[i] = lg[t + i * 256]; m = fmaxf(m, v[i]); }

    __shared__ float redm[8];
    #pragma unroll
    for (int o = 16; o > 0; o >>= 1) m = fmaxf(m, __shfl_xor_sync(0xffffffffu, m, o));
    if ((t & 31) == 0) redm[t >> 5] = m;
    __syncthreads();
    m = redm[0];
    #pragma unroll
    for (int i = 1; i < 8; ++i) m = fmaxf(m, redm[i]);

    float sl = 0.f;
    #pragma unroll
    for (int i = 0; i < 4; ++i) { v[i] = __expf(v[i] - m); sl += v[i]; }
    __shared__ float reds[8];
    #pragma unroll
    for (int o = 16; o > 0; o >>= 1) sl += __shfl_xor_sync(0xffffffffu, sl, o);
    if ((t & 31) == 0) reds[t >> 5] = sl;
    __syncthreads();
    float tot = 0.f;
    #pragma unroll
    for (int i = 0; i < 8; ++i) tot += reds[i];
    float inv = 1.0f / tot;

    float* op = out + ((size_t)b * AA + a) * SS;
    #pragma unroll
    for (int i = 0; i < 4; ++i) op[t + i * 256] = v[i] * inv;
}

// ---------------------------------------------------------------------------
// K4: ctx partials. grid = (B, 8), block = 128 (4 warps).
// Warp w owns s in [w*32, w*32+32) of its 128-s chunk; lane = h-quad, so each
// warp LDG.128 covers one full 512B doc row. 4-warp smem reduce (pitch RPW,
// conflict-free), then coalesced store of one coarse partial per chunk.
// ---------------------------------------------------------------------------
__global__ void __launch_bounds__(128) k_ctx(const float* __restrict__ doc,
                                             const float* __restrict__ attn) {
    int b = blockIdx.x, sc = blockIdx.y;
    int t = threadIdx.x, w = t >> 5, lane = t & 31;

    __shared__ float asmem[AA * CCH];     // 4KB
    __shared__ float rbuf[4 * RPW];       // 16.4KB
    #pragma unroll
    for (int i = t; i < AA * CCH; i += 128) {
        int a = i >> 7, s = i & 127;
        asmem[i] = attn[((size_t)b * AA + a) * SS + sc * CCH + s];
    }
    __syncthreads();

    const float4* dp = (const float4*)(doc + ((size_t)b * SS + sc * CCH) * HH) + lane;
    unsigned long long acc[AA][2];
    #pragma unroll
    for (int a = 0; a < AA; ++a) { acc[a][0] = 0ull; acc[a][1] = 0ull; }

    int sb = w * 32;
    #pragma unroll 8
    for (int i = 0; i < 32; ++i) {
        int s = sb + i;
        float4 dv = dp[s * 32];                    // coalesced 512B/warp LDG.128
        unsigned long long dxy = pk2(dv.x, dv.y);
        unsigned long long dzw = pk2(dv.z, dv.w);
        #pragma unroll
        for (int a = 0; a < AA; ++a) {
            unsigned long long av = dup2(asmem[a * CCH + s]);   // broadcast
            fma2(acc[a][0], dxy, av);
            fma2(acc[a][1], dzw, av);
        }
    }

    #pragma unroll
    for (int a = 0; a < AA; ++a) {
        float4 o;
        unpk(acc[a][0], o.x, o.y);
        unpk(acc[a][1], o.z, o.w);
        *(float4*)&rbuf[w * RPW + a * HH + lane * 4] = o;   // conflict-free STS.128
    }
    __syncthreads();

    // Reduce over the 4 warps: thread t -> h = t; k -> aspect.
    #pragma unroll
    for (int k = 0; k < AA; ++k) {
        int slot = k * HH + t;
        float v = (rbuf[slot] + rbuf[RPW + slot]) +
                  (rbuf[2 * RPW + slot] + rbuf[3 * RPW + slot]);
        gCtxPart[(((size_t)sc * AA + k) * BB + b) * HH + t] = v;   // coalesced
    }
}

// ---------------------------------------------------------------------------
// K5: rep[b,a,f] = sum_h ctx[a,b,h] * P[a,h,f], ctx reduced over 8 partials
// grid = B*A (blk = b*A + a), block = 128 (thread = f)
// ---------------------------------------------------------------------------
__global__ void k_rep(const float* __restrict__ P, float* __restrict__ out) {
    int blk = blockIdx.x;
    int a = blk & 7, b = blk >> 3;
    int f = threadIdx.x;
    __shared__ float csm[HH];
    float c = 0.f;
    #pragma unroll
    for (int sc = 0; sc < NCH; ++sc)
        c += gCtxPart[(((size_t)sc * AA + a) * BB + b) * HH + f];
    csm[f] = c;
    __syncthreads();

    float acc = 0.f;
    const float* Pp = P + (size_t)a * HH * HH + f;
    #pragma unroll 8
    for (int h = 0; h < HH; ++h) acc += csm[h] * Pp[(size_t)h * HH];

    out[(size_t)BB * AA * SS + ((size_t)b * AA + a) * HH + f] = acc;
}

// ---------------------------------------------------------------------------
extern "C" void kernel_launch(void* const* d_in, const int* in_sizes, int n_in,
                              void* d_out, int out_size) {
    const float* doc = (const float*)d_in[0];   // (B,S,H)
    const float* E   = (const float*)d_in[1];   // (A, WIN*H)
    const float* P   = (const float*)d_in[2];   // (A,H,H)
    float* out = (float*)d_out;                 // [attn (B,A,S) | rep (B,A,H)]

    size_t sm2 = (size_t)(GROWS * HH + HH * WIN * 8) * sizeof(float);  // ~88.1 KB
    cudaFuncSetAttribute(k_logits, cudaFuncAttributeMaxDynamicSharedMemorySize, (int)sm2);

    k_prep<<<dim3(AA, 4), 128>>>(P, E);
    k_logits<<<dim3(SS / STILE, BB), 128, sm2>>>(doc);
    k_softmax<<<AA * BB, 256>>>(out);
    k_ctx<<<dim3(BB, NCH), 128>>>(doc, out);
    k_rep<<<BB * AA, 128>>>(P, out);
}